// round 12
// baseline (speedup 1.0000x reference)
#include <cuda_runtime.h>
#include <cstdint>

#define N_TOK  32768
#define KDIM   2048
#define NEXP   64
#define TOPK   6
#define TM     128             // tokens per CTA
#define KC     32              // K per staged chunk
#define NCHUNK (KDIM / KC)     // 64
#define LDROW  132             // padded smem row (floats); 132*4B = 33*16B -> rows 16B-aligned

#define STAGE_F    (2 * KC * LDROW)           // floats per stage (As + Bd)
#define SMEM_BYTES (2 * STAGE_F * 4)          // 67584 B

// scratch for scores (allocation-free rule: __device__ global)
__device__ float g_scores[(size_t)N_TOK * NEXP];

// ---- packed fp32x2 helpers (Blackwell FFMA2 path) ----
__device__ __forceinline__ unsigned long long fma2(unsigned long long a,
                                                   unsigned long long b,
                                                   unsigned long long c) {
    unsigned long long d;
    asm("fma.rn.f32x2 %0, %1, %2, %3;" : "=l"(d) : "l"(a), "l"(b), "l"(c));
    return d;
}
__device__ __forceinline__ float2 unpackff(unsigned long long v) {
    float2 f;
    asm("mov.b64 {%0, %1}, %2;" : "=f"(f.x), "=f"(f.y) : "l"(v));
    return f;
}

// ============================================================
// Kernel 1: scores[t][e] = sum_d x[t][d] * w[e][d]   (fp32)
// CTA: 128 tokens x 64 experts, 256 threads (8 warps),
// thread tile 8 tokens x 4 experts -> 4 warps/SMSP at 2 CTA/SM.
// Double-buffered smem, one __syncthreads per chunk.
// Accumulation: single ascending-k FFMA.rn chain per element ->
// scores bitwise identical to the validated 266.8us kernel.
// ============================================================
__global__ __launch_bounds__(256, 2)
void gemm_scores_kernel(const float* __restrict__ x, const float* __restrict__ w) {
    extern __shared__ float smem[];
    const int tid = threadIdx.x;
    const int tx  = tid & 15;         // expert group: experts {16j+tx, j=0..3}
    const int ty  = tid >> 4;         // token group: tokens ty*8 .. ty*8+7
    const int t0  = blockIdx.x * TM;

    // acc[p][j]: token pair (ty*8+2p, +1) x expert (16j+tx)
    unsigned long long acc[4][4];
#pragma unroll
    for (int p = 0; p < 4; p++)
#pragma unroll
        for (int j = 0; j < 4; j++) acc[p][j] = 0ull;

    float4 ra[4], rb[2];
    // ---- prefetch chunk 0 ----
#pragma unroll
    for (int i = 0; i < 4; i++) {
        int gi = tid + 256 * i, row = gi >> 3, c16 = gi & 7;
        ra[i] = *(const float4*)(x + (size_t)(t0 + row) * KDIM + c16 * 4);
    }
#pragma unroll
    for (int i = 0; i < 2; i++) {
        int gi = tid + 256 * i, row = gi >> 3, c16 = gi & 7;
        rb[i] = *(const float4*)(w + (size_t)row * KDIM + c16 * 4);
    }
    // ---- store chunk 0 into stage 0 ----
    {
        float* As = smem;
        float* Bd = smem + KC * LDROW;
#pragma unroll
        for (int i = 0; i < 4; i++) {
            int gi = tid + 256 * i, row = gi >> 3, k4 = (gi & 7) * 4;
            As[(k4 + 0) * LDROW + row] = ra[i].x;
            As[(k4 + 1) * LDROW + row] = ra[i].y;
            As[(k4 + 2) * LDROW + row] = ra[i].z;
            As[(k4 + 3) * LDROW + row] = ra[i].w;
        }
#pragma unroll
        for (int i = 0; i < 2; i++) {
            int gi = tid + 256 * i, row = gi >> 3, k4 = (gi & 7) * 4;
            *(float2*)&Bd[(k4 + 0) * LDROW + 2 * row] = make_float2(rb[i].x, rb[i].x);
            *(float2*)&Bd[(k4 + 1) * LDROW + 2 * row] = make_float2(rb[i].y, rb[i].y);
            *(float2*)&Bd[(k4 + 2) * LDROW + 2 * row] = make_float2(rb[i].z, rb[i].z);
            *(float2*)&Bd[(k4 + 3) * LDROW + 2 * row] = make_float2(rb[i].w, rb[i].w);
        }
    }
    __syncthreads();

    for (int c = 0; c < NCHUNK; c++) {
        const float* As = smem + (c & 1) * STAGE_F;
        const float* Bd = As + KC * LDROW;

        // issue LDG for chunk c+1 (hidden behind compute)
        if (c + 1 < NCHUNK) {
            const int k0 = (c + 1) * KC;
#pragma unroll
            for (int i = 0; i < 4; i++) {
                int gi = tid + 256 * i, row = gi >> 3, c16 = gi & 7;
                ra[i] = *(const float4*)(x + (size_t)(t0 + row) * KDIM + k0 + c16 * 4);
            }
#pragma unroll
            for (int i = 0; i < 2; i++) {
                int gi = tid + 256 * i, row = gi >> 3, c16 = gi & 7;
                rb[i] = *(const float4*)(w + (size_t)row * KDIM + k0 + c16 * 4);
            }
        }

        // compute: 32 ascending k-steps on stage (c&1)
#pragma unroll 8
        for (int kk = 0; kk < KC; kk++) {
            unsigned long long a[4], b[4];
            const float4 av0 = *(const float4*)&As[kk * LDROW + ty * 8];
            const float4 av1 = *(const float4*)&As[kk * LDROW + ty * 8 + 4];
            a[0] = *(const unsigned long long*)&av0.x;
            a[1] = *(const unsigned long long*)&av0.z;
            a[2] = *(const unsigned long long*)&av1.x;
            a[3] = *(const unsigned long long*)&av1.z;
#pragma unroll
            for (int j = 0; j < 4; j++)
                b[j] = *(const unsigned long long*)&Bd[kk * LDROW + 2 * (16 * j + tx)];
#pragma unroll
            for (int p = 0; p < 4; p++)
#pragma unroll
                for (int j = 0; j < 4; j++)
                    acc[p][j] = fma2(a[p], b[j], acc[p][j]);
        }

        // store chunk c+1 into the other stage
        if (c + 1 < NCHUNK) {
            float* As2 = smem + ((c + 1) & 1) * STAGE_F;
            float* Bd2 = As2 + KC * LDROW;
#pragma unroll
            for (int i = 0; i < 4; i++) {
                int gi = tid + 256 * i, row = gi >> 3, k4 = (gi & 7) * 4;
                As2[(k4 + 0) * LDROW + row] = ra[i].x;
                As2[(k4 + 1) * LDROW + row] = ra[i].y;
                As2[(k4 + 2) * LDROW + row] = ra[i].z;
                As2[(k4 + 3) * LDROW + row] = ra[i].w;
            }
#pragma unroll
            for (int i = 0; i < 2; i++) {
                int gi = tid + 256 * i, row = gi >> 3, k4 = (gi & 7) * 4;
                *(float2*)&Bd2[(k4 + 0) * LDROW + 2 * row] = make_float2(rb[i].x, rb[i].x);
                *(float2*)&Bd2[(k4 + 1) * LDROW + 2 * row] = make_float2(rb[i].y, rb[i].y);
                *(float2*)&Bd2[(k4 + 2) * LDROW + 2 * row] = make_float2(rb[i].z, rb[i].z);
                *(float2*)&Bd2[(k4 + 3) * LDROW + 2 * row] = make_float2(rb[i].w, rb[i].w);
            }
            __syncthreads();
        }
    }

    // epilogue: write scores
#pragma unroll
    for (int p = 0; p < 4; p++) {
        const int tok = t0 + ty * 8 + 2 * p;
#pragma unroll
        for (int j = 0; j < 4; j++) {
            float2 v = unpackff(acc[p][j]);
            const int e = 16 * j + tx;
            g_scores[(size_t)tok * NEXP + e]       = v.x;
            g_scores[(size_t)(tok + 1) * NEXP + e] = v.y;
        }
    }
}

// FTZ emulation of XLA-GPU softmax tail (validated):
// exp below FLT_MIN -> 0.0; division result below FLT_MIN -> 0.0.
// Flushed experts tie at 0.0 -> top_k stable order = ascending index.
#define FLT_MIN_N 1.17549435082228751e-38f
__device__ __forceinline__ float exp_ftz(float x) {
    float e = expf(x);
    return (e < FLT_MIN_N) ? 0.0f : e;
}

// ============================================================
// Kernel 2: softmax over 64 experts + top-6 (warp per token).
// (byte-for-byte the validated round-10 kernel)
// out: [N_TOK*TOPK] weights fp32, then [N_TOK*TOPK] indices as fp32
// ============================================================
__global__ __launch_bounds__(256)
void softmax_topk_kernel(float* __restrict__ out, int write_idx) {
    const int warp = threadIdx.x >> 5;
    const int lane = threadIdx.x & 31;
    const int t = blockIdx.x * 8 + warp;
    if (t >= N_TOK) return;

    const float* s = g_scores + (size_t)t * NEXP;
    float v0 = s[lane];
    float v1 = s[lane + 32];

    float m = fmaxf(v0, v1);
#pragma unroll
    for (int o = 16; o; o >>= 1) m = fmaxf(m, __shfl_xor_sync(0xffffffffu, m, o));

    float e0 = exp_ftz(v0 - m);
    float e1 = exp_ftz(v1 - m);
    float sum = e0 + e1;
#pragma unroll
    for (int o = 16; o; o >>= 1) sum += __shfl_xor_sync(0xffffffffu, sum, o);

    float p0 = __fdiv_rn(e0, sum);
    float p1 = __fdiv_rn(e1, sum);
    if (p0 < FLT_MIN_N) p0 = 0.0f;   // ftz division output
    if (p1 < FLT_MIN_N) p1 = 0.0f;

#pragma unroll
    for (int j = 0; j < TOPK; j++) {
        float bv; int bi;
        if (p0 >= p1) { bv = p0; bi = lane; }       // tie -> smaller index
        else          { bv = p1; bi = lane + 32; }
#pragma unroll
        for (int o = 16; o; o >>= 1) {
            float ov = __shfl_xor_sync(0xffffffffu, bv, o);
            int   oi = __shfl_xor_sync(0xffffffffu, bi, o);
            if (ov > bv || (ov == bv && oi < bi)) { bv = ov; bi = oi; }
        }
        if (lane == 0) {
            out[(size_t)t * TOPK + j] = bv;          // ROUTE_SCALE = 1
            if (write_idx)
                out[(size_t)N_TOK * TOPK + (size_t)t * TOPK + j] = (float)bi;
        }
        if (bi == lane)      p0 = -1.0f;
        if (bi == lane + 32) p1 = -1.0f;
    }
}

extern "C" void kernel_launch(void* const* d_in, const int* in_sizes, int n_in,
                              void* d_out, int out_size) {
    const float* x = (const float*)d_in[0];   // [32768, 2048] fp32
    const float* w = (const float*)d_in[1];   // [64, 2048] fp32
    float* out = (float*)d_out;

    static int smem_set = 0;
    if (!smem_set) {
        cudaFuncSetAttribute(gemm_scores_kernel,
                             cudaFuncAttributeMaxDynamicSharedMemorySize, SMEM_BYTES);
        smem_set = 1;
    }

    gemm_scores_kernel<<<N_TOK / TM, 256, SMEM_BYTES>>>(x, w);

    const int write_idx = (out_size >= 2 * N_TOK * TOPK) ? 1 : 0;
    softmax_topk_kernel<<<N_TOK / 8, 256>>>(out, write_idx);
}

// round 15
// speedup vs baseline: 1.0781x; 1.0781x over previous
#include <cuda_runtime.h>
#include <cstdint>

#define N_TOK  32768
#define KDIM   2048
#define NEXP   64
#define TOPK   6
#define TM     64              // tokens per CTA (GEMM)
#define KC     32              // K per staged chunk
#define NCHUNK (KDIM / KC)     // 64
#define LDPAD  36              // padded row (floats); 144B rows, 16B-aligned

// scratch for scores (allocation-free rule: __device__ global)
__device__ float g_scores[(size_t)N_TOK * NEXP];

// TF32 round-to-nearest-away (cuBLAS/cutlass conversion)
__device__ __forceinline__ float tf32r(float x) {
    uint32_t r;
    asm("cvt.rna.tf32.f32 %0, %1;" : "=r"(r) : "f"(x));
    return __uint_as_float(r);
}

#define MMA_TF32(acc, A0, A1, A2, A3, B0, B1)                                  \
    asm volatile(                                                              \
        "mma.sync.aligned.m16n8k8.row.col.f32.tf32.tf32.f32 "                  \
        "{%0,%1,%2,%3}, {%4,%5,%6,%7}, {%8,%9}, {%0,%1,%2,%3};"                \
        : "+f"(acc[0]), "+f"(acc[1]), "+f"(acc[2]), "+f"(acc[3])               \
        : "r"(A0), "r"(A1), "r"(A2), "r"(A3), "r"(B0), "r"(B1))

// ============================================================
// Kernel 1: scores = x @ w^T via 3xTF32 mma.sync (m16n8k8).
// (exact round-13 kernel; score noise vs reference ~4e-5 —
//  handled by the fixup in kernel 2)
// ============================================================
__global__ __launch_bounds__(128)
void gemm_3xtf32_kernel(const float* __restrict__ x, const float* __restrict__ w) {
    __shared__ float Ah[TM * LDPAD];
    __shared__ float Al[TM * LDPAD];
    __shared__ float Bh[NEXP * LDPAD];
    __shared__ float Bl[NEXP * LDPAD];

    const int tid  = threadIdx.x;
    const int lane = tid & 31;
    const int wid  = tid >> 5;
    const int t0   = blockIdx.x * TM;
    const int r4   = lane >> 2;
    const int c4   = lane & 3;

    float acc[8][4] = {};

    float4 ra[4], rb[4];
#pragma unroll
    for (int i = 0; i < 4; i++) {
        int gi = tid + 128 * i, row = gi >> 3, cc = gi & 7;
        ra[i] = *(const float4*)(x + (size_t)(t0 + row) * KDIM + cc * 4);
        rb[i] = *(const float4*)(w + (size_t)row * KDIM + cc * 4);
    }

    for (int c = 0; c < NCHUNK; c++) {
        __syncthreads();
#pragma unroll
        for (int i = 0; i < 4; i++) {
            int gi = tid + 128 * i, row = gi >> 3, cc = gi & 7;
            float4 v = ra[i];
            float4 h, l;
            h.x = tf32r(v.x); l.x = tf32r(v.x - h.x);
            h.y = tf32r(v.y); l.y = tf32r(v.y - h.y);
            h.z = tf32r(v.z); l.z = tf32r(v.z - h.z);
            h.w = tf32r(v.w); l.w = tf32r(v.w - h.w);
            *(float4*)&Ah[row * LDPAD + cc * 4] = h;
            *(float4*)&Al[row * LDPAD + cc * 4] = l;
            v = rb[i];
            h.x = tf32r(v.x); l.x = tf32r(v.x - h.x);
            h.y = tf32r(v.y); l.y = tf32r(v.y - h.y);
            h.z = tf32r(v.z); l.z = tf32r(v.z - h.z);
            h.w = tf32r(v.w); l.w = tf32r(v.w - h.w);
            *(float4*)&Bh[row * LDPAD + cc * 4] = h;
            *(float4*)&Bl[row * LDPAD + cc * 4] = l;
        }
        __syncthreads();

        if (c + 1 < NCHUNK) {
            const int k0 = (c + 1) * KC;
#pragma unroll
            for (int i = 0; i < 4; i++) {
                int gi = tid + 128 * i, row = gi >> 3, cc = gi & 7;
                ra[i] = *(const float4*)(x + (size_t)(t0 + row) * KDIM + k0 + cc * 4);
                rb[i] = *(const float4*)(w + (size_t)row * KDIM + k0 + cc * 4);
            }
        }

#pragma unroll
        for (int ks = 0; ks < 4; ks++) {
            const int kk = ks * 8;
            const int arow = wid * 16 + r4;
            uint32_t ah0 = __float_as_uint(Ah[(arow)     * LDPAD + kk + c4]);
            uint32_t ah1 = __float_as_uint(Ah[(arow + 8) * LDPAD + kk + c4]);
            uint32_t ah2 = __float_as_uint(Ah[(arow)     * LDPAD + kk + c4 + 4]);
            uint32_t ah3 = __float_as_uint(Ah[(arow + 8) * LDPAD + kk + c4 + 4]);
            uint32_t al0 = __float_as_uint(Al[(arow)     * LDPAD + kk + c4]);
            uint32_t al1 = __float_as_uint(Al[(arow + 8) * LDPAD + kk + c4]);
            uint32_t al2 = __float_as_uint(Al[(arow)     * LDPAD + kk + c4 + 4]);
            uint32_t al3 = __float_as_uint(Al[(arow + 8) * LDPAD + kk + c4 + 4]);
#pragma unroll
            for (int nb = 0; nb < 8; nb++) {
                const int brow = nb * 8 + r4;
                uint32_t bh0 = __float_as_uint(Bh[brow * LDPAD + kk + c4]);
                uint32_t bh1 = __float_as_uint(Bh[brow * LDPAD + kk + c4 + 4]);
                uint32_t bl0 = __float_as_uint(Bl[brow * LDPAD + kk + c4]);
                uint32_t bl1 = __float_as_uint(Bl[brow * LDPAD + kk + c4 + 4]);
                MMA_TF32(acc[nb], ah0, ah1, ah2, ah3, bh0, bh1);  // hi*hi
                MMA_TF32(acc[nb], ah0, ah1, ah2, ah3, bl0, bl1);  // hi*lo
                MMA_TF32(acc[nb], al0, al1, al2, al3, bh0, bh1);  // lo*hi
            }
        }
    }

    const int row0 = t0 + wid * 16 + r4;
#pragma unroll
    for (int nb = 0; nb < 8; nb++) {
        *(float2*)(g_scores + (size_t)row0 * NEXP + nb * 8 + 2 * c4) =
            make_float2(acc[nb][0], acc[nb][1]);
        *(float2*)(g_scores + (size_t)(row0 + 8) * NEXP + nb * 8 + 2 * c4) =
            make_float2(acc[nb][2], acc[nb][3]);
    }
}

// FTZ emulation of XLA-GPU softmax tail (validated round 9/10):
#define FLT_MIN_N 1.17549435082228751e-38f
__device__ __forceinline__ float exp_ftz(float x) {
    float e = expf(x);
    return (e < FLT_MIN_N) ? 0.0f : e;
}
// cutoff-proximity band: value within 0.5% of FLT_MIN (d-band ~1e-2 >> max noise 2e-4)
__device__ __forceinline__ bool near_ftz(float v) {
    return v > 0.995f * FLT_MIN_N && v < 1.005f * FLT_MIN_N;
}
#define GAP_EPS 1e-3f   // score-gap ambiguity band (max tensor noise ~2e-4)

// ============================================================
// Kernel 2: softmax + top-6 with ambiguity detection and exact
// FFMA recompute (bitwise = validated fp32 chain) for flagged
// tokens. Warp per token.
// out: [N_TOK*TOPK] weights fp32, then [N_TOK*TOPK] indices as fp32
// ============================================================
__global__ __launch_bounds__(256)
void softmax_topk_fix_kernel(const float* __restrict__ x, const float* __restrict__ w,
                             float* __restrict__ out, int write_idx) {
    const int warp = threadIdx.x >> 5;
    const int lane = threadIdx.x & 31;
    const int t = blockIdx.x * 8 + warp;
    if (t >= N_TOK) return;

    const float* s = g_scores + (size_t)t * NEXP;
    float v0 = s[lane];
    float v1 = s[lane + 32];

    for (int pass = 0; pass < 2; pass++) {
        const bool exact = (pass == 1);

        float m = fmaxf(v0, v1);
#pragma unroll
        for (int o = 16; o; o >>= 1) m = fmaxf(m, __shfl_xor_sync(0xffffffffu, m, o));

        float e0 = exp_ftz(v0 - m);
        float e1 = exp_ftz(v1 - m);
        float sum = e0 + e1;
#pragma unroll
        for (int o = 16; o; o >>= 1) sum += __shfl_xor_sync(0xffffffffu, sum, o);

        float p0r = __fdiv_rn(e0, sum);
        float p1r = __fdiv_rn(e1, sum);
        bool nf = false;
        if (!exact) nf = near_ftz(e0) || near_ftz(e1) || near_ftz(p0r) || near_ftz(p1r);
        float p0 = (p0r < FLT_MIN_N) ? 0.0f : p0r;
        float p1 = (p1r < FLT_MIN_N) ? 0.0f : p1r;

        // 7 selection rounds on (p, smallest-index tiebreak), carrying d = s - m.
        float wv[6]; int we[6];
        float pv0 = p0, pv1 = p1;
        bool gapflag = false;
        float dprev = 0.0f;
#pragma unroll
        for (int r = 0; r < 7; r++) {
            float bv, bd; int bi;
            if (pv0 >= pv1) { bv = pv0; bi = lane;      bd = v0 - m; }
            else            { bv = pv1; bi = lane + 32; bd = v1 - m; }
#pragma unroll
            for (int o = 16; o; o >>= 1) {
                float ov = __shfl_xor_sync(0xffffffffu, bv, o);
                int   oi = __shfl_xor_sync(0xffffffffu, bi, o);
                float od = __shfl_xor_sync(0xffffffffu, bd, o);
                if (ov > bv || (ov == bv && oi < bi)) { bv = ov; bi = oi; bd = od; }
            }
            if (r > 0 && bv > 0.0f && (dprev - bd) < GAP_EPS) gapflag = true;
            dprev = bd;
            if (r < 6) { wv[r] = bv; we[r] = bi; }
            if (bi == lane)      pv0 = -1.0f;
            if (bi == lane + 32) pv1 = -1.0f;
        }

        bool flagged = (!exact) && (gapflag || __any_sync(0xffffffffu, nf));
        if (!flagged) {
            if (lane == 0) {
#pragma unroll
                for (int r = 0; r < TOPK; r++) {
                    out[(size_t)t * TOPK + r] = wv[r];       // ROUTE_SCALE = 1
                    if (write_idx)
                        out[(size_t)N_TOK * TOPK + (size_t)t * TOPK + r] = (float)we[r];
                }
            }
            return;
        }

        // ---- exact recompute: ascending-k fmaf chain (bitwise = validated
        //      fp32 GEMM per-element arithmetic) for all 64 experts ----
        {
            const float4* xr = (const float4*)(x + (size_t)t * KDIM);
            const float4* w0 = (const float4*)(w + (size_t)lane * KDIM);
            const float4* w1 = (const float4*)(w + (size_t)(lane + 32) * KDIM);
            float a0 = 0.0f, a1 = 0.0f;
#pragma unroll 4
            for (int k4 = 0; k4 < KDIM / 4; k4++) {
                float4 xv = xr[k4];
                float4 u  = w0[k4];
                float4 q  = w1[k4];
                a0 = fmaf(xv.x, u.x, a0); a1 = fmaf(xv.x, q.x, a1);
                a0 = fmaf(xv.y, u.y, a0); a1 = fmaf(xv.y, q.y, a1);
                a0 = fmaf(xv.z, u.z, a0); a1 = fmaf(xv.z, q.z, a1);
                a0 = fmaf(xv.w, u.w, a0); a1 = fmaf(xv.w, q.w, a1);
            }
            v0 = a0;
            v1 = a1;
        }
        // loop continues: pass 1 redoes softmax + selection on exact scores
    }
}

extern "C" void kernel_launch(void* const* d_in, const int* in_sizes, int n_in,
                              void* d_out, int out_size) {
    const float* x = (const float*)d_in[0];   // [32768, 2048] fp32
    const float* w = (const float*)d_in[1];   // [64, 2048] fp32
    float* out = (float*)d_out;

    gemm_3xtf32_kernel<<<N_TOK / TM, 128>>>(x, w);

    const int write_idx = (out_size >= 2 * N_TOK * TOPK) ? 1 : 0;
    softmax_topk_fix_kernel<<<N_TOK / 8, 256>>>(x, w, out, write_idx);
}